// round 1
// baseline (speedup 1.0000x reference)
#include <cuda_runtime.h>

// out[n, f, h] = x[n, f] * W[f, h] + b[f, h]
// BATCH=16384, F=128, H=64, all fp32.
// Store-bound: 512 MiB out, 8 MiB x, 64 KiB W+b.
// One float4 store per thread; 16 lanes cover one (n,f) row of H=64.

#define BATCH 16384
#define NFEAT 128
#define HID   64
#define H4    (HID / 4)          // 16 float4 per (n,f) row
#define TOTAL_F4 (BATCH * NFEAT * H4)   // 33,554,432

__global__ __launch_bounds__(256)
void ifll_kernel(const float* __restrict__ x,
                 const float4* __restrict__ W4,
                 const float4* __restrict__ b4,
                 float4* __restrict__ out)
{
    int idx = blockIdx.x * blockDim.x + threadIdx.x;
    if (idx >= TOTAL_F4) return;

    int h4 = idx & (H4 - 1);        // which float4 within the hidden row
    int nf = idx >> 4;              // flattened (n, f); x is [N, F] contiguous
    int f  = nf & (NFEAT - 1);

    float xv = __ldg(&x[nf]);                 // uniform across the 16-lane group
    float4 w = __ldg(&W4[f * H4 + h4]);       // L1/L2 resident (64 KiB total)
    float4 bb = __ldg(&b4[f * H4 + h4]);

    float4 o;
    o.x = fmaf(xv, w.x, bb.x);
    o.y = fmaf(xv, w.y, bb.y);
    o.z = fmaf(xv, w.z, bb.z);
    o.w = fmaf(xv, w.w, bb.w);
    out[idx] = o;
}

extern "C" void kernel_launch(void* const* d_in, const int* in_sizes, int n_in,
                              void* d_out, int out_size)
{
    const float*  x  = (const float*)d_in[0];
    const float4* W4 = (const float4*)d_in[1];
    const float4* b4 = (const float4*)d_in[2];
    float4* out = (float4*)d_out;

    const int threads = 256;
    const int blocks  = TOTAL_F4 / threads;   // 131072, exact division
    ifll_kernel<<<blocks, threads>>>(x, W4, b4, out);
}

// round 2
// speedup vs baseline: 1.4932x; 1.4932x over previous
#include <cuda_runtime.h>

// out[n, f, h] = x[n, f] * W[f, h] + b[f, h]
// BATCH=16384, F=128, H=64, fp32. Output 512 MiB -> pure streaming-store bound.
//
// Each thread owns one (f, h4) pair: loads its W/b float4 ONCE into registers,
// then loops over 16 batch rows doing 1 x-load (broadcast within 16-lane group)
// + 1 STG.128 per row. Warp = 2 adjacent f values x 16 h4 -> each store is a
// fully-contiguous 512 B segment. __stcs: 512 MiB output is 4x L2, don't cache.

#define BATCH 16384
#define NFEAT 128
#define HID   64
#define H4    (HID / 4)               // 16
#define FH    (NFEAT * H4)            // 2048 (f,h4) pairs
#define TPB   256
#define FH_BLOCKS (FH / TPB)          // 8
#define N_PER_THREAD 16
#define N_CHUNKS (BATCH / N_PER_THREAD) // 1024

__global__ __launch_bounds__(TPB)
void ifll_kernel(const float* __restrict__ x,
                 const float4* __restrict__ W4,
                 const float4* __restrict__ b4,
                 float4* __restrict__ out)
{
    // blockIdx.x = n_chunk * FH_BLOCKS + f_block
    int fh = (blockIdx.x & (FH_BLOCKS - 1)) * TPB + threadIdx.x; // 0..2047
    int n0 = (blockIdx.x >> 3) * N_PER_THREAD;

    int f = fh >> 4;                  // feature index

    // Per-thread invariant weights: loaded once, amortized over 16 rows.
    float4 w  = __ldg(&W4[fh]);       // W4[f*H4 + h4] == W4[fh]
    float4 bb = __ldg(&b4[fh]);

    const float* xp = x + (size_t)n0 * NFEAT + f;
    float4*      op = out + (size_t)n0 * FH + fh;

    #pragma unroll
    for (int i = 0; i < N_PER_THREAD; i++) {
        float xv = __ldg(xp + i * NFEAT);
        float4 o;
        o.x = fmaf(xv, w.x, bb.x);
        o.y = fmaf(xv, w.y, bb.y);
        o.z = fmaf(xv, w.z, bb.z);
        o.w = fmaf(xv, w.w, bb.w);
        __stcs(op + (size_t)i * FH, o);   // streaming store, evict-first
    }
}

extern "C" void kernel_launch(void* const* d_in, const int* in_sizes, int n_in,
                              void* d_out, int out_size)
{
    const float*  x  = (const float*)d_in[0];
    const float4* W4 = (const float4*)d_in[1];
    const float4* b4 = (const float4*)d_in[2];
    float4* out = (float4*)d_out;

    const int blocks = N_CHUNKS * FH_BLOCKS;  // 8192
    ifll_kernel<<<blocks, TPB>>>(x, W4, b4, out);
}

// round 4
// speedup vs baseline: 1.5152x; 1.0147x over previous
#include <cuda_runtime.h>

// out[n, f, h] = x[n, f] * W[f, h] + b[f, h]
// BATCH=16384, F=128, H=64, fp32. Output 512 MiB -> pure streaming-store bound.
//
// R2: each thread owns one (f, h4) pair and 16 batch rows. All 16 x loads are
// front-batched (MLP=16) so the 16 STG.128s issue as an uninterrupted store
// stream with no exposed load latency. W/b live in registers for the whole
// thread. __stcs: output is 4x L2 capacity, evict-first.

#define BATCH 16384
#define NFEAT 128
#define HID   64
#define H4    (HID / 4)               // 16
#define FH    (NFEAT * H4)            // 2048 (f,h4) pairs
#define TPB   256
#define FH_BLOCKS (FH / TPB)          // 8
#define N_PER_THREAD 16
#define N_CHUNKS (BATCH / N_PER_THREAD) // 1024

__global__ __launch_bounds__(TPB)
void ifll_kernel(const float* __restrict__ x,
                 const float4* __restrict__ W4,
                 const float4* __restrict__ b4,
                 float4* __restrict__ out)
{
    // blockIdx.x = n_chunk * FH_BLOCKS + f_block
    int fh = (blockIdx.x & (FH_BLOCKS - 1)) * TPB + threadIdx.x; // 0..2047
    int n0 = (blockIdx.x >> 3) * N_PER_THREAD;

    int f = fh >> 4;                  // feature index

    float4 w  = __ldg(&W4[fh]);
    float4 bb = __ldg(&b4[fh]);

    const float* xp = x + (size_t)n0 * NFEAT + f;
    float4*      op = out + (size_t)n0 * FH + fh;

    // Front-batch all x loads: 16 independent LDGs in flight.
    float xv[N_PER_THREAD];
    #pragma unroll
    for (int i = 0; i < N_PER_THREAD; i++)
        xv[i] = __ldg(xp + i * NFEAT);

    // Pure store stream.
    #pragma unroll
    for (int i = 0; i < N_PER_THREAD; i++) {
        float4 o;
        o.x = fmaf(xv[i], w.x, bb.x);
        o.y = fmaf(xv[i], w.y, bb.y);
        o.z = fmaf(xv[i], w.z, bb.z);
        o.w = fmaf(xv[i], w.w, bb.w);
        __stcs(op + (size_t)i * FH, o);
    }
}

extern "C" void kernel_launch(void* const* d_in, const int* in_sizes, int n_in,
                              void* d_out, int out_size)
{
    const float*  x  = (const float*)d_in[0];
    const float4* W4 = (const float4*)d_in[1];
    const float4* b4 = (const float4*)d_in[2];
    float4* out = (float4*)d_out;

    const int blocks = N_CHUNKS * FH_BLOCKS;  // 8192
    ifll_kernel<<<blocks, TPB>>>(x, W4, b4, out);
}